// round 13
// baseline (speedup 1.0000x reference)
#include <cuda_runtime.h>
#include <cuda_bf16.h>
#include <cstdint>

#define Bb 4096
#define Tt 128
#define Ff 64
#define Hh 32

typedef unsigned long long u64;

// xz in gate-pair-interleaved u64 form: xzp[row][p] with
//   p in [0,32):  (z_i[p],    z_f[p])      = (z[p],    z[32+p])
//   p in [32,64): (z_g[p-32], z_o[p-32])   = (z[64+q], z[96+q])
__device__ u64 g_xzp[(size_t)Bb * Tt * 64];

// B images for HMMA: Bt[n][k] = We[k][n], bf16 hi/lo, plain [128][64]
__device__ __align__(16) unsigned short g_Bth[128 * 64];
__device__ __align__(16) unsigned short g_Btl[128 * 64];
// be packed into gate-pair u64s
__device__ u64 g_bep[64];

// ---------- f32x2 packed helpers ----------
__device__ __forceinline__ u64 pk2(float lo, float hi) {
    u64 r; asm("mov.b64 %0, {%1, %2};" : "=l"(r) : "f"(lo), "f"(hi)); return r;
}
__device__ __forceinline__ void upk2(u64 v, float &lo, float &hi) {
    asm("mov.b64 {%0, %1}, %2;" : "=f"(lo), "=f"(hi) : "l"(v));
}
__device__ __forceinline__ u64 fma2(u64 a, u64 b, u64 c) {
    u64 d; asm("fma.rn.f32x2 %0, %1, %2, %3;" : "=l"(d) : "l"(a), "l"(b), "l"(c)); return d;
}
__device__ __forceinline__ u64 add2(u64 a, u64 b) {
    u64 d; asm("add.rn.f32x2 %0, %1, %2;" : "=l"(d) : "l"(a), "l"(b)); return d;
}

// ---------- cp.async helpers ----------
__device__ __forceinline__ void cpa16(void* dst, const void* src) {
    unsigned ds = (unsigned)__cvta_generic_to_shared(dst);
    asm volatile("cp.async.ca.shared.global [%0], [%1], 16;" :: "r"(ds), "l"(src));
}
__device__ __forceinline__ void cpa_commit() {
    asm volatile("cp.async.commit_group;");
}
template<int N> __device__ __forceinline__ void cpa_wait() {
    asm volatile("cp.async.wait_group %0;" :: "n"(N));
}

__device__ __forceinline__ float sigf(float x) {
    return __fdividef(1.0f, 1.0f + __expf(-x));
}
__device__ __forceinline__ float cellf(float zi, float zf, float zg, float zo, float &c) {
    float i = sigf(zi);
    float f = sigf(zf);
    float g = fmaxf(zg, 0.0f);
    float o = sigf(zo);
    c = fmaf(f, c, i * g);
    return o * fmaxf(c, 0.0f);
}

__device__ __forceinline__ unsigned short bf16bits(float f) {
    __nv_bfloat16 b = __float2bfloat16(f);
    return *reinterpret_cast<unsigned short*>(&b);
}
__device__ __forceinline__ float bf16val(unsigned short s) {
    __nv_bfloat16 b = *reinterpret_cast<__nv_bfloat16*>(&s);
    return __bfloat162float(b);
}

// mma.sync m16n8k16 bf16 -> f32 (sm_80+ PTX, works on sm_103 base target)
__device__ __forceinline__ void mma16816(float* d,
                                         uint32_t a0, uint32_t a1, uint32_t a2, uint32_t a3,
                                         uint32_t b0, uint32_t b1) {
    asm volatile("mma.sync.aligned.m16n8k16.row.col.f32.bf16.bf16.f32 "
                 "{%0,%1,%2,%3}, {%4,%5,%6,%7}, {%8,%9}, {%0,%1,%2,%3};"
                 : "+f"(d[0]), "+f"(d[1]), "+f"(d[2]), "+f"(d[3])
                 : "r"(a0), "r"(a1), "r"(a2), "r"(a3), "r"(b0), "r"(b1));
}

// SMEM layout for k_xz (dynamic). bf16 rows padded to 72 elems (144B).
#define AS_HI 0
#define AS_LO 9216
#define BS_HI 18432
#define BS_LO 36864
#define SMX_TOTAL 55296

// =====================================================================
// Kernel 0: prep — bf16 hi/lo images of B (Bt[n][k] = We[k][n]) + be pairs.
// (coalesced-enough once; keeps the per-CTA path clean)
// =====================================================================
__global__ void k_prep(const float* __restrict__ We, const float* __restrict__ be)
{
    const int tid = threadIdx.x;
    for (int e = tid; e < 128 * 64; e += 256) {
        int n = e >> 6, k = e & 63;
        float v = __ldg(We + k * 128 + n);
        unsigned short hi = bf16bits(v);
        unsigned short lo = bf16bits(v - bf16val(hi));
        g_Bth[n * 64 + k] = hi;
        g_Btl[n * 64 + k] = lo;
    }
    for (int p = tid; p < 64; p += 256) {
        int a = (p < 32) ? p : (64 + (p - 32));
        g_bep[p] = pk2(__ldg(be + a), __ldg(be + a + 32));
    }
}

// =====================================================================
// Kernel 1: xz = x @ We + be via mma.sync bf16-split (3 terms).
// (verbatim round-11 version: ~148us)
// =====================================================================
__global__ __launch_bounds__(128) void k_xz(const float* __restrict__ x)
{
    extern __shared__ __align__(16) char sm[];
    const int tid = threadIdx.x;
    const int wid = tid >> 5;
    const int lane = tid & 31;
    const int g = lane >> 2, t = lane & 3;

    for (int i = tid; i < 1024; i += 128) {
        int row = i >> 3, grp = i & 7;
        *(uint4*)(sm + BS_HI + row * 144 + grp * 16) = __ldg((const uint4*)g_Bth + i);
        *(uint4*)(sm + BS_LO + row * 144 + grp * 16) = __ldg((const uint4*)g_Btl + i);
    }
    {
        const float4* xb = (const float4*)(x + (size_t)blockIdx.x * 64 * 64);
        for (int i = tid; i < 1024; i += 128) {
            int row = i >> 4, kq = i & 15;
            float4 v = __ldg(xb + i);
            float vs[4] = {v.x, v.y, v.z, v.w};
            unsigned short hi[4], lo[4];
#pragma unroll
            for (int j = 0; j < 4; j++) {
                hi[j] = bf16bits(vs[j]);
                lo[j] = bf16bits(vs[j] - bf16val(hi[j]));
            }
            *(uint2*)(sm + AS_HI + row * 144 + kq * 8) = *(uint2*)hi;
            *(uint2*)(sm + AS_LO + row * 144 + kq * 8) = *(uint2*)lo;
        }
    }
    __syncthreads();

    const int rowlo = wid * 16;
    const char* Ah = sm + AS_HI + (rowlo + g) * 144 + t * 4;
    const char* Al = sm + AS_LO + (rowlo + g) * 144 + t * 4;
    const char* Bh = sm + BS_HI + g * 144 + t * 4;
    const char* Bl = sm + BS_LO + g * 144 + t * 4;

    float acc[16][4];
#pragma unroll
    for (int j = 0; j < 16; j++)
#pragma unroll
        for (int q = 0; q < 4; q++) acc[j][q] = 0.0f;

#pragma unroll
    for (int ks = 0; ks < 4; ks++) {
        const int ko = ks * 32;
        uint32_t ah0 = *(const uint32_t*)(Ah + ko);
        uint32_t ah1 = *(const uint32_t*)(Ah + ko + 1152);
        uint32_t ah2 = *(const uint32_t*)(Ah + ko + 16);
        uint32_t ah3 = *(const uint32_t*)(Ah + ko + 1152 + 16);
        uint32_t al0 = *(const uint32_t*)(Al + ko);
        uint32_t al1 = *(const uint32_t*)(Al + ko + 1152);
        uint32_t al2 = *(const uint32_t*)(Al + ko + 16);
        uint32_t al3 = *(const uint32_t*)(Al + ko + 1152 + 16);
#pragma unroll
        for (int j = 0; j < 16; j++) {
            const char* bh = Bh + j * 1152 + ko;
            const char* bl = Bl + j * 1152 + ko;
            uint32_t bh0 = *(const uint32_t*)bh;
            uint32_t bh1 = *(const uint32_t*)(bh + 16);
            uint32_t bl0 = *(const uint32_t*)bl;
            uint32_t bl1 = *(const uint32_t*)(bl + 16);
            mma16816(acc[j], ah0, ah1, ah2, ah3, bh0, bh1);
            mma16816(acc[j], al0, al1, al2, al3, bh0, bh1);
            mma16816(acc[j], ah0, ah1, ah2, ah3, bl0, bl1);
        }
    }

    const size_t r0 = (size_t)blockIdx.x * 64 + rowlo + g;
    const size_t r1 = r0 + 8;
#pragma unroll
    for (int half = 0; half < 2; half++) {
#pragma unroll
        for (int jj = 0; jj < 4; jj++) {
            int j = half * 8 + jj;
            int p = half * 32 + jj * 8 + 2 * t;
            ulonglong2 bb = *(const ulonglong2*)&g_bep[p];
            ulonglong2 s0, s1;
            s0.x = add2(pk2(acc[j][0], acc[j + 4][0]), bb.x);
            s0.y = add2(pk2(acc[j][1], acc[j + 4][1]), bb.y);
            s1.x = add2(pk2(acc[j][2], acc[j + 4][2]), bb.x);
            s1.y = add2(pk2(acc[j][3], acc[j + 4][3]), bb.y);
            *(ulonglong2*)&g_xzp[r0 * 64 + p] = s0;
            *(ulonglong2*)&g_xzp[r1 * 64 + p] = s1;
        }
    }
}

// =====================================================================
// Kernel 2: fused encoder + decoder + Dense(64), 4-WARP teams, 8-kk
// slices. CTA = 128 thr = 4 warps = 4 batch rows. Warp w owns
// kk in [8w, 8w+8) (U slice = 32 regs) and finalizes row w. Per step
// each warp accumulates partials for all 4 rows over its slice;
// non-own partials exchanged via smem. 6 CTAs/SM (24 warps).
// =====================================================================
__global__ __launch_bounds__(128, 6) void k_rnn(const float* __restrict__ Ue,
                                                const float* __restrict__ Ud,
                                                const float* __restrict__ Wd,
                                                const float* __restrict__ bd,
                                                const float* __restrict__ Wout,
                                                const float* __restrict__ bout,
                                                float* __restrict__ y)
{
    __shared__ __align__(16) u64 Wos[32 * 32];      // 8KB
    __shared__ __align__(16) u64 ring[4][4][64];    // 8KB [warp][slot][idx]
    __shared__ __align__(16) u64 hds[2][4][32];     // 2KB [buf][row][kk]
    __shared__ __align__(16) u64 px[4][4][3][32];   // 12KB [srcw][row][v][lane]

    const int tid = threadIdx.x;
    const int lane = tid & 31;
    const int wid = tid >> 5;
    const int row = blockIdx.x * 4 + wid;           // row this warp finalizes
    const int base = wid * 8;                       // owned kk slice

    for (int i = tid; i < 32 * 32; i += 128) {
        int kk = i >> 5, l = i & 31;
        Wos[i] = pk2(__ldg(Wout + kk * 64 + l), __ldg(Wout + kk * 64 + 32 + l));
    }

    // ---------------- encoder ----------------
    u64 wif[8], wgo[8];
#pragma unroll
    for (int j = 0; j < 8; j++) {
        const float* u = Ue + (base + j) * 128;
        wif[j] = pk2(__ldg(u + lane),      __ldg(u + 32 + lane));
        wgo[j] = pk2(__ldg(u + 64 + lane), __ldg(u + 96 + lane));
    }

    const u64* xzr = g_xzp + (size_t)row * 128 * 64;
#pragma unroll
    for (int p = 0; p < 3; p++) {
        cpa16(&ring[wid][p][lane * 2], xzr + (size_t)p * 64 + lane * 2);
        cpa_commit();
    }

    hds[0][wid][lane] = 0ULL;
    hds[1][wid][lane] = 0ULL;
    cpa_wait<2>();
    __syncthreads();

    float h = 0.f, cc = 0.f;

    for (int t = 0; t < 128; t++) {
        const int cb = t & 1;
        const u64* slot = ring[wid][t & 3];

        u64 aif[4] = {0ULL, 0ULL, 0ULL, 0ULL};
        u64 ago[4] = {0ULL, 0ULL, 0ULL, 0ULL};

        if (t < 125) {
            cpa16(&ring[wid][(t + 3) & 3][lane * 2],
                  xzr + (size_t)(t + 3) * 64 + lane * 2);
            cpa_commit();
        }

#pragma unroll
        for (int j = 0; j < 8; j++) {
#pragma unroll
            for (int r = 0; r < 4; r++) {
                u64 hD = hds[cb][r][base + j];
                aif[r] = fma2(hD, wif[j], aif[r]);
                ago[r] = fma2(hD, wgo[j], ago[r]);
            }
        }

        // publish non-own partials; keep own in regs
        u64 aifm = 0ULL, agom = 0ULL;
#pragma unroll
        for (int r = 0; r < 4; r++) {
            if (r == wid) { aifm = aif[r]; agom = ago[r]; }
            else {
                px[wid][r][0][lane] = aif[r];
                px[wid][r][1][lane] = ago[r];
            }
        }
        __syncthreads();
#pragma unroll
        for (int ow = 0; ow < 4; ow++) {
            if (ow != wid) {
                aifm = add2(aifm, px[ow][wid][0][lane]);
                agom = add2(agom, px[ow][wid][1][lane]);
            }
        }
        aifm = add2(aifm, slot[lane]);
        agom = add2(agom, slot[32 + lane]);

        float zi, zf, zg, zo;
        upk2(aifm, zi, zf); upk2(agom, zg, zo);
        h = cellf(zi, zf, zg, zo, cc);

        hds[cb ^ 1][wid][lane] = pk2(h, h);
        if (t < 125) cpa_wait<2>(); else cpa_wait<0>();
        __syncthreads();
    }

    // ---------------- zd = hT @ Wd + bd (warp-local, once) ----------------
    u64 zif = pk2(__ldg(bd + lane),      __ldg(bd + 32 + lane));
    u64 zgo = pk2(__ldg(bd + 64 + lane), __ldg(bd + 96 + lane));
    {
        float ht = h;
#pragma unroll
        for (int kk = 0; kk < 32; kk++) {
            float hv = __shfl_sync(0xffffffffu, ht, kk);
            const float* w = Wd + kk * 128;
            u64 hp = pk2(hv, hv);
            zif = fma2(hp, pk2(__ldg(w + lane),      __ldg(w + 32 + lane)), zif);
            zgo = fma2(hp, pk2(__ldg(w + 64 + lane), __ldg(w + 96 + lane)), zgo);
        }
    }

    // ---------------- decoder (reload U = Ud slice) ----------------
#pragma unroll
    for (int j = 0; j < 8; j++) {
        const float* u = Ud + (base + j) * 128;
        wif[j] = pk2(__ldg(u + lane),      __ldg(u + 32 + lane));
        wgo[j] = pk2(__ldg(u + 64 + lane), __ldg(u + 96 + lane));
    }

    hds[0][wid][lane] = 0ULL;
    hds[1][wid][lane] = 0ULL;
    __syncthreads();

    h = 0.f; cc = 0.f;
    u64 bo = pk2(__ldg(bout + lane), __ldg(bout + 32 + lane));
    float* y0 = y + (size_t)row * 128 * 64;

    for (int t = 0; t < 128; t++) {
        const int cb = t & 1;

        u64 aif[4] = {0ULL, 0ULL, 0ULL, 0ULL};
        u64 ago[4] = {0ULL, 0ULL, 0ULL, 0ULL};
        u64 ya[4]  = {0ULL, 0ULL, 0ULL, 0ULL};

#pragma unroll
        for (int j = 0; j < 8; j++) {
            u64 wo = Wos[(base + j) * 32 + lane];
#pragma unroll
            for (int r = 0; r < 4; r++) {
                u64 hD = hds[cb][r][base + j];
                aif[r] = fma2(hD, wif[j], aif[r]);
                ago[r] = fma2(hD, wgo[j], ago[r]);
                ya[r]  = fma2(hD, wo, ya[r]);
            }
        }

        u64 aifm = 0ULL, agom = 0ULL, yam = 0ULL;
#pragma unroll
        for (int r = 0; r < 4; r++) {
            if (r == wid) { aifm = aif[r]; agom = ago[r]; yam = ya[r]; }
            else {
                px[wid][r][0][lane] = aif[r];
                px[wid][r][1][lane] = ago[r];
                px[wid][r][2][lane] = ya[r];
            }
        }
        __syncthreads();
#pragma unroll
        for (int ow = 0; ow < 4; ow++) {
            if (ow != wid) {
                aifm = add2(aifm, px[ow][wid][0][lane]);
                agom = add2(agom, px[ow][wid][1][lane]);
                yam  = add2(yam,  px[ow][wid][2][lane]);
            }
        }
        aifm = add2(aifm, zif);
        agom = add2(agom, zgo);
        yam  = add2(yam, bo);

        if (t > 0) {   // yam used h_t = hs[t-1] -> y[t-1]
            float a, b;
            upk2(yam, a, b);
            y0[(size_t)(t - 1) * 64 + lane] = a;
            y0[(size_t)(t - 1) * 64 + 32 + lane] = b;
        }

        float zi, zf, zg, zo;
        upk2(aifm, zi, zf); upk2(agom, zg, zo);
        h = cellf(zi, zf, zg, zo, cc);

        hds[cb ^ 1][wid][lane] = pk2(h, h);
        __syncthreads();
    }

    // epilogue: y[127] from h_128 (hds buf 0 after t=127)
    {
        const u64* hcm = hds[0][wid];
        u64 ya0 = bo, ya1 = 0ULL;
#pragma unroll
        for (int kk = 0; kk < 32; kk += 2) {
            ya0 = fma2(hcm[kk],     Wos[kk * 32 + lane],       ya0);
            ya1 = fma2(hcm[kk + 1], Wos[(kk + 1) * 32 + lane], ya1);
        }
        u64 ya = add2(ya0, ya1);
        float a, b;
        upk2(ya, a, b);
        y0[(size_t)127 * 64 + lane] = a;
        y0[(size_t)127 * 64 + 32 + lane] = b;
    }
}

// =====================================================================
extern "C" void kernel_launch(void* const* d_in, const int* in_sizes, int n_in,
                              void* d_out, int out_size)
{
    const float* x    = (const float*)d_in[0];
    const float* We   = (const float*)d_in[1];
    const float* Ue   = (const float*)d_in[2];
    const float* be   = (const float*)d_in[3];
    const float* Wd   = (const float*)d_in[4];
    const float* Ud   = (const float*)d_in[5];
    const float* bd   = (const float*)d_in[6];
    const float* Wout = (const float*)d_in[7];
    const float* bout = (const float*)d_in[8];
    float* y = (float*)d_out;

    cudaFuncSetAttribute(k_xz, cudaFuncAttributeMaxDynamicSharedMemorySize, SMX_TOTAL);

    k_prep<<<1, 256>>>(We, be);
    k_xz<<<8192, 128, SMX_TOTAL>>>(x);
    k_rnn<<<1024, 128>>>(Ue, Ud, Wd, bd, Wout, bout, y);
}

// round 14
// speedup vs baseline: 1.2784x; 1.2784x over previous
#include <cuda_runtime.h>
#include <cuda_bf16.h>
#include <cstdint>

#define Bb 4096
#define Tt 128
#define Ff 64
#define Hh 32

typedef unsigned long long u64;

// xz in gate-pair-interleaved u64 form: xzp[row][p] with
//   p in [0,32):  (z_i[p],    z_f[p])      = (z[p],    z[32+p])
//   p in [32,64): (z_g[p-32], z_o[p-32])   = (z[64+q], z[96+q])
__device__ u64 g_xzp[(size_t)Bb * Tt * 64];

// B images for HMMA: Bt[n][k] = We[k][n], bf16 hi/lo, plain [128][64]
__device__ __align__(16) unsigned short g_Bth[128 * 64];
__device__ __align__(16) unsigned short g_Btl[128 * 64];
// be packed into gate-pair u64s
__device__ u64 g_bep[64];

// ---------- f32x2 packed helpers ----------
__device__ __forceinline__ u64 pk2(float lo, float hi) {
    u64 r; asm("mov.b64 %0, {%1, %2};" : "=l"(r) : "f"(lo), "f"(hi)); return r;
}
__device__ __forceinline__ void upk2(u64 v, float &lo, float &hi) {
    asm("mov.b64 {%0, %1}, %2;" : "=f"(lo), "=f"(hi) : "l"(v));
}
__device__ __forceinline__ u64 fma2(u64 a, u64 b, u64 c) {
    u64 d; asm("fma.rn.f32x2 %0, %1, %2, %3;" : "=l"(d) : "l"(a), "l"(b), "l"(c)); return d;
}
__device__ __forceinline__ u64 add2(u64 a, u64 b) {
    u64 d; asm("add.rn.f32x2 %0, %1, %2;" : "=l"(d) : "l"(a), "l"(b)); return d;
}

// ---------- cp.async helpers ----------
__device__ __forceinline__ void cpa16(void* dst, const void* src) {
    unsigned ds = (unsigned)__cvta_generic_to_shared(dst);
    asm volatile("cp.async.ca.shared.global [%0], [%1], 16;" :: "r"(ds), "l"(src));
}
__device__ __forceinline__ void cpa_commit() {
    asm volatile("cp.async.commit_group;");
}
template<int N> __device__ __forceinline__ void cpa_wait() {
    asm volatile("cp.async.wait_group %0;" :: "n"(N));
}

__device__ __forceinline__ float sigf(float x) {
    return __fdividef(1.0f, 1.0f + __expf(-x));
}
__device__ __forceinline__ float cellf(float zi, float zf, float zg, float zo, float &c) {
    float i = sigf(zi);
    float f = sigf(zf);
    float g = fmaxf(zg, 0.0f);
    float o = sigf(zo);
    c = fmaf(f, c, i * g);
    return o * fmaxf(c, 0.0f);
}

__device__ __forceinline__ unsigned short bf16bits(float f) {
    __nv_bfloat16 b = __float2bfloat16(f);
    return *reinterpret_cast<unsigned short*>(&b);
}
__device__ __forceinline__ float bf16val(unsigned short s) {
    __nv_bfloat16 b = *reinterpret_cast<__nv_bfloat16*>(&s);
    return __bfloat162float(b);
}

// mma.sync m16n8k16 bf16 -> f32 (sm_80+ PTX, works on sm_103 base target)
__device__ __forceinline__ void mma16816(float* d,
                                         uint32_t a0, uint32_t a1, uint32_t a2, uint32_t a3,
                                         uint32_t b0, uint32_t b1) {
    asm volatile("mma.sync.aligned.m16n8k16.row.col.f32.bf16.bf16.f32 "
                 "{%0,%1,%2,%3}, {%4,%5,%6,%7}, {%8,%9}, {%0,%1,%2,%3};"
                 : "+f"(d[0]), "+f"(d[1]), "+f"(d[2]), "+f"(d[3])
                 : "r"(a0), "r"(a1), "r"(a2), "r"(a3), "r"(b0), "r"(b1));
}

// SMEM layout for k_xz (dynamic). bf16 rows padded to 72 elems (144B).
#define AS_HI 0
#define AS_LO 9216
#define BS_HI 18432
#define BS_LO 36864
#define SMX_TOTAL 55296

// =====================================================================
// Kernel 0: prep — bf16 hi/lo images of B (Bt[n][k] = We[k][n]) + be pairs.
// =====================================================================
__global__ void k_prep(const float* __restrict__ We, const float* __restrict__ be)
{
    const int tid = threadIdx.x;
    for (int e = tid; e < 128 * 64; e += 256) {
        int n = e >> 6, k = e & 63;
        float v = __ldg(We + k * 128 + n);
        unsigned short hi = bf16bits(v);
        unsigned short lo = bf16bits(v - bf16val(hi));
        g_Bth[n * 64 + k] = hi;
        g_Btl[n * 64 + k] = lo;
    }
    for (int p = tid; p < 64; p += 256) {
        int a = (p < 32) ? p : (64 + (p - 32));
        g_bep[p] = pk2(__ldg(be + a), __ldg(be + a + 32));
    }
}

// =====================================================================
// Kernel 1: xz = x @ We + be via mma.sync bf16-split (verbatim R11, ~148us)
// =====================================================================
__global__ __launch_bounds__(128) void k_xz(const float* __restrict__ x)
{
    extern __shared__ __align__(16) char sm[];
    const int tid = threadIdx.x;
    const int wid = tid >> 5;
    const int lane = tid & 31;
    const int g = lane >> 2, t = lane & 3;

    for (int i = tid; i < 1024; i += 128) {
        int row = i >> 3, grp = i & 7;
        *(uint4*)(sm + BS_HI + row * 144 + grp * 16) = __ldg((const uint4*)g_Bth + i);
        *(uint4*)(sm + BS_LO + row * 144 + grp * 16) = __ldg((const uint4*)g_Btl + i);
    }
    {
        const float4* xb = (const float4*)(x + (size_t)blockIdx.x * 64 * 64);
        for (int i = tid; i < 1024; i += 128) {
            int row = i >> 4, kq = i & 15;
            float4 v = __ldg(xb + i);
            float vs[4] = {v.x, v.y, v.z, v.w};
            unsigned short hi[4], lo[4];
#pragma unroll
            for (int j = 0; j < 4; j++) {
                hi[j] = bf16bits(vs[j]);
                lo[j] = bf16bits(vs[j] - bf16val(hi[j]));
            }
            *(uint2*)(sm + AS_HI + row * 144 + kq * 8) = *(uint2*)hi;
            *(uint2*)(sm + AS_LO + row * 144 + kq * 8) = *(uint2*)lo;
        }
    }
    __syncthreads();

    const int rowlo = wid * 16;
    const char* Ah = sm + AS_HI + (rowlo + g) * 144 + t * 4;
    const char* Al = sm + AS_LO + (rowlo + g) * 144 + t * 4;
    const char* Bh = sm + BS_HI + g * 144 + t * 4;
    const char* Bl = sm + BS_LO + g * 144 + t * 4;

    float acc[16][4];
#pragma unroll
    for (int j = 0; j < 16; j++)
#pragma unroll
        for (int q = 0; q < 4; q++) acc[j][q] = 0.0f;

#pragma unroll
    for (int ks = 0; ks < 4; ks++) {
        const int ko = ks * 32;
        uint32_t ah0 = *(const uint32_t*)(Ah + ko);
        uint32_t ah1 = *(const uint32_t*)(Ah + ko + 1152);
        uint32_t ah2 = *(const uint32_t*)(Ah + ko + 16);
        uint32_t ah3 = *(const uint32_t*)(Ah + ko + 1152 + 16);
        uint32_t al0 = *(const uint32_t*)(Al + ko);
        uint32_t al1 = *(const uint32_t*)(Al + ko + 1152);
        uint32_t al2 = *(const uint32_t*)(Al + ko + 16);
        uint32_t al3 = *(const uint32_t*)(Al + ko + 1152 + 16);
#pragma unroll
        for (int j = 0; j < 16; j++) {
            const char* bh = Bh + j * 1152 + ko;
            const char* bl = Bl + j * 1152 + ko;
            uint32_t bh0 = *(const uint32_t*)bh;
            uint32_t bh1 = *(const uint32_t*)(bh + 16);
            uint32_t bl0 = *(const uint32_t*)bl;
            uint32_t bl1 = *(const uint32_t*)(bl + 16);
            mma16816(acc[j], ah0, ah1, ah2, ah3, bh0, bh1);
            mma16816(acc[j], al0, al1, al2, al3, bh0, bh1);
            mma16816(acc[j], ah0, ah1, ah2, ah3, bl0, bl1);
        }
    }

    const size_t r0 = (size_t)blockIdx.x * 64 + rowlo + g;
    const size_t r1 = r0 + 8;
#pragma unroll
    for (int half = 0; half < 2; half++) {
#pragma unroll
        for (int jj = 0; jj < 4; jj++) {
            int j = half * 8 + jj;
            int p = half * 32 + jj * 8 + 2 * t;
            ulonglong2 bb = *(const ulonglong2*)&g_bep[p];
            ulonglong2 s0, s1;
            s0.x = add2(pk2(acc[j][0], acc[j + 4][0]), bb.x);
            s0.y = add2(pk2(acc[j][1], acc[j + 4][1]), bb.y);
            s1.x = add2(pk2(acc[j][2], acc[j + 4][2]), bb.x);
            s1.y = add2(pk2(acc[j][3], acc[j + 4][3]), bb.y);
            *(ulonglong2*)&g_xzp[r0 * 64 + p] = s0;
            *(ulonglong2*)&g_xzp[r1 * 64 + p] = s1;
        }
    }
}

// =====================================================================
// Kernel 2: fused encoder + decoder + Dense(64), K-SPLIT 2-warp teams
// (R9 structure, known-good 300us) + ONE change: all broadcast h reads
// widened to LDS.128 (ulonglong2) — halves the broadcast wavefronts
// that saturate the L1 crossbar (measured L1=79%).
// CTA = 64 threads = 2 warps = 2 batch rows. 2048 CTAs.
// =====================================================================
__global__ __launch_bounds__(64) void k_rnn(const float* __restrict__ Ue,
                                            const float* __restrict__ Ud,
                                            const float* __restrict__ Wd,
                                            const float* __restrict__ bd,
                                            const float* __restrict__ Wout,
                                            const float* __restrict__ bout,
                                            float* __restrict__ y)
{
    __shared__ __align__(16) u64 Wos[32 * 32];     // 8KB: (Wout[kk][l], Wout[kk][32+l])
    __shared__ __align__(16) u64 ring[2][4][64];   // 4KB xz ring per row
    __shared__ __align__(16) u64 hds[2][2][32];    // [buf][row][kk] h duplicated
    __shared__ __align__(16) u64 px[2][3][32];     // cross partials [srcwarp][v][lane]

    const int tid = threadIdx.x;
    const int lane = tid & 31;
    const int wid = tid >> 5;
    const int ow = wid ^ 1;
    const int row = blockIdx.x * 2 + wid;          // row this warp finalizes
    const int base = wid * 16;                     // owned kk range

    for (int i = tid; i < 32 * 32; i += 64) {
        int kk = i >> 5, l = i & 31;
        Wos[i] = pk2(__ldg(Wout + kk * 64 + l), __ldg(Wout + kk * 64 + 32 + l));
    }

    // ---------------- encoder ----------------
    u64 wif[16], wgo[16];
#pragma unroll
    for (int j = 0; j < 16; j++) {
        const float* u = Ue + (base + j) * 128;
        wif[j] = pk2(__ldg(u + lane),      __ldg(u + 32 + lane));
        wgo[j] = pk2(__ldg(u + 64 + lane), __ldg(u + 96 + lane));
    }

    const u64* xzr = g_xzp + (size_t)row * 128 * 64;
#pragma unroll
    for (int p = 0; p < 3; p++) {
        cpa16(&ring[wid][p][lane * 2], xzr + (size_t)p * 64 + lane * 2);
        cpa_commit();
    }

    hds[0][wid][lane] = 0ULL;
    hds[1][wid][lane] = 0ULL;
    cpa_wait<2>();
    __syncthreads();

    float h = 0.f, cc = 0.f;

    for (int t = 0; t < 128; t++) {
        const int cb = t & 1;
        const u64* hcm = hds[cb][wid];   // my row's h
        const u64* hco = hds[cb][ow];    // other row's h
        const u64* slot = ring[wid][t & 3];

        u64 aifm = slot[lane], agom = slot[32 + lane];   // my row: init xz
        u64 aifo = 0ULL, agoo = 0ULL;                    // other row partial

        if (t < 125) {
            cpa16(&ring[wid][(t + 3) & 3][lane * 2],
                  xzr + (size_t)(t + 3) * 64 + lane * 2);
            cpa_commit();
        }

#pragma unroll
        for (int j = 0; j < 16; j += 2) {
            ulonglong2 hm2 = *(const ulonglong2*)&hcm[base + j];   // LDS.128 bcast
            ulonglong2 ho2 = *(const ulonglong2*)&hco[base + j];
            aifm = fma2(hm2.x, wif[j], aifm);
            agom = fma2(hm2.x, wgo[j], agom);
            aifo = fma2(ho2.x, wif[j], aifo);
            agoo = fma2(ho2.x, wgo[j], agoo);
            aifm = fma2(hm2.y, wif[j + 1], aifm);
            agom = fma2(hm2.y, wgo[j + 1], agom);
            aifo = fma2(ho2.y, wif[j + 1], aifo);
            agoo = fma2(ho2.y, wgo[j + 1], agoo);
        }

        px[wid][0][lane] = aifo;
        px[wid][1][lane] = agoo;
        __syncthreads();
        u64 aif = add2(aifm, px[ow][0][lane]);
        u64 ago = add2(agom, px[ow][1][lane]);

        float zi, zf, zg, zo;
        upk2(aif, zi, zf); upk2(ago, zg, zo);
        h = cellf(zi, zf, zg, zo, cc);

        hds[cb ^ 1][wid][lane] = pk2(h, h);
        if (t < 125) cpa_wait<2>(); else cpa_wait<0>();
        __syncthreads();
    }

    // ---------------- zd = hT @ Wd + bd (warp-local, once) ----------------
    u64 zif = pk2(__ldg(bd + lane),      __ldg(bd + 32 + lane));
    u64 zgo = pk2(__ldg(bd + 64 + lane), __ldg(bd + 96 + lane));
    {
        float ht = h;
#pragma unroll
        for (int kk = 0; kk < 32; kk++) {
            float hv = __shfl_sync(0xffffffffu, ht, kk);
            const float* w = Wd + kk * 128;
            u64 hp = pk2(hv, hv);
            zif = fma2(hp, pk2(__ldg(w + lane),      __ldg(w + 32 + lane)), zif);
            zgo = fma2(hp, pk2(__ldg(w + 64 + lane), __ldg(w + 96 + lane)), zgo);
        }
    }

    // ---------------- decoder (reload U = Ud slice) ----------------
#pragma unroll
    for (int j = 0; j < 16; j++) {
        const float* u = Ud + (base + j) * 128;
        wif[j] = pk2(__ldg(u + lane),      __ldg(u + 32 + lane));
        wgo[j] = pk2(__ldg(u + 64 + lane), __ldg(u + 96 + lane));
    }

    hds[0][wid][lane] = 0ULL;
    hds[1][wid][lane] = 0ULL;
    __syncthreads();

    h = 0.f; cc = 0.f;
    u64 bo = pk2(__ldg(bout + lane), __ldg(bout + 32 + lane));
    float* y0 = y + (size_t)row * 128 * 64;

    for (int t = 0; t < 128; t++) {
        const int cb = t & 1;
        const u64* hcm = hds[cb][wid];
        const u64* hco = hds[cb][ow];

        u64 aifm = zif, agom = zgo, yam = bo;
        u64 aifo = 0ULL, agoo = 0ULL, yao = 0ULL;

#pragma unroll
        for (int j = 0; j < 16; j += 2) {
            ulonglong2 hm2 = *(const ulonglong2*)&hcm[base + j];   // LDS.128 bcast
            ulonglong2 ho2 = *(const ulonglong2*)&hco[base + j];
            u64 wo0 = Wos[(base + j) * 32 + lane];
            u64 wo1 = Wos[(base + j + 1) * 32 + lane];
            aifm = fma2(hm2.x, wif[j], aifm);
            agom = fma2(hm2.x, wgo[j], agom);
            yam  = fma2(hm2.x, wo0, yam);
            aifo = fma2(ho2.x, wif[j], aifo);
            agoo = fma2(ho2.x, wgo[j], agoo);
            yao  = fma2(ho2.x, wo0, yao);
            aifm = fma2(hm2.y, wif[j + 1], aifm);
            agom = fma2(hm2.y, wgo[j + 1], agom);
            yam  = fma2(hm2.y, wo1, yam);
            aifo = fma2(ho2.y, wif[j + 1], aifo);
            agoo = fma2(ho2.y, wgo[j + 1], agoo);
            yao  = fma2(ho2.y, wo1, yao);
        }

        px[wid][0][lane] = aifo;
        px[wid][1][lane] = agoo;
        px[wid][2][lane] = yao;
        __syncthreads();
        u64 aif = add2(aifm, px[ow][0][lane]);
        u64 ago = add2(agom, px[ow][1][lane]);
        u64 ya  = add2(yam,  px[ow][2][lane]);

        if (t > 0) {   // ya used h_t = hs[t-1] -> y[t-1]
            float a, b;
            upk2(ya, a, b);
            y0[(size_t)(t - 1) * 64 + lane] = a;
            y0[(size_t)(t - 1) * 64 + 32 + lane] = b;
        }

        float zi, zf, zg, zo;
        upk2(aif, zi, zf); upk2(ago, zg, zo);
        h = cellf(zi, zf, zg, zo, cc);

        hds[cb ^ 1][wid][lane] = pk2(h, h);
        __syncthreads();
    }

    // epilogue: y[127] from h_128 (hds buf 0 after t=127; synced in-loop)
    {
        const u64* hcm = hds[0][wid];
        u64 ya0 = bo, ya1 = 0ULL;
#pragma unroll
        for (int kk = 0; kk < 32; kk += 2) {
            ulonglong2 h2 = *(const ulonglong2*)&hcm[kk];
            ya0 = fma2(h2.x, Wos[kk * 32 + lane],       ya0);
            ya1 = fma2(h2.y, Wos[(kk + 1) * 32 + lane], ya1);
        }
        u64 ya = add2(ya0, ya1);
        float a, b;
        upk2(ya, a, b);
        y0[(size_t)127 * 64 + lane] = a;
        y0[(size_t)127 * 64 + 32 + lane] = b;
    }
}

// =====================================================================
extern "C" void kernel_launch(void* const* d_in, const int* in_sizes, int n_in,
                              void* d_out, int out_size)
{
    const float* x    = (const float*)d_in[0];
    const float* We   = (const float*)d_in[1];
    const float* Ue   = (const float*)d_in[2];
    const float* be   = (const float*)d_in[3];
    const float* Wd   = (const float*)d_in[4];
    const float* Ud   = (const float*)d_in[5];
    const float* bd   = (const float*)d_in[6];
    const float* Wout = (const float*)d_in[7];
    const float* bout = (const float*)d_in[8];
    float* y = (float*)d_out;

    cudaFuncSetAttribute(k_xz, cudaFuncAttributeMaxDynamicSharedMemorySize, SMX_TOTAL);

    k_prep<<<1, 256>>>(We, be);
    k_xz<<<8192, 128, SMX_TOTAL>>>(x);
    k_rnn<<<2048, 64>>>(Ue, Ud, Wd, bd, Wout, bout, y);
}